// round 12
// baseline (speedup 1.0000x reference)
#include <cuda_runtime.h>
#include <math.h>

#define NB       1024
#define LSCALE   128.0f
#define KPRE     300
#define KOUT     10
#define SORTN    512
#define CANDCAP  512
#define NW       32
#define WSEG     96
#define FLATCAP  3072
#define RAW_T0   340
#define FULLM    0xFFFFFFFFu

// group scratch for lvl0 4-way split (static: no allocation)
__device__ int2 g_cand[16][FLATCAP];
__device__ int  g_gcnt[16];
__device__ int  g_arrive[16];
__device__ int  g_ovf[16];

struct Ptrs {
    const float* cls[4];
    const float* box[4];
    const float* anc[4];
};

// grid 112 = 16 batches x (4 lvl0 parts + lvl1 + lvl2 + lvl3). Each CTA
// streams ~equal element counts. lvl0 parts export filtered candidates to
// global; last-arriving CTA of the group merges and runs the full pipeline
// (hist -> exact cut -> decode -> 512 bitonic sort -> NMS). Others local.
__global__ __launch_bounds__(1024) void detect_kernel(Ptrs P, float* out, int out_size) {
    const int pid = blockIdx.x;
    const int b   = pid / 7;
    const int sub = pid % 7;
    const int lvl  = (sub < 4) ? 0 : (sub - 3);
    const int part = (sub < 4) ? sub : 0;
    const int HW  = 16384 >> (2*lvl);
    const int N   = 9 * HW;
    const int n4full = N >> 2;
    const int p4  = (lvl == 0) ? (n4full >> 2) : n4full;
    const int i0  = part * p4;
    const int flBK = (lvl==0) ? 336 : (lvl==1) ? 256 : (lvl==2) ? 160 : 64;
    const float floorVal = (float)flBK * (1.0f/128.0f);   // exact
    const float* cls  = P.cls[lvl] + (size_t)b * N;
    const float* boxp = P.box[lvl];
    const float* anc  = P.anc[lvl];
    const int tid = threadIdx.x, wid = tid >> 5, lane = tid & 31;

    __shared__ int   hist[NB];
    __shared__ float cval[FLATCAP];
    __shared__ int   cidx[FLATCAP];
    __shared__ unsigned long long sKey[SORTN];
    __shared__ float4 candBox[CANDCAP];
    __shared__ int   wtot[32];
    __shared__ int   s_seg[NW];
    __shared__ int   s_woff[NW];
    __shared__ int   s_ccnt, s_base, s_last, s_ovf;
    __shared__ int   s_gcnt, s_govf;
    __shared__ int   s_cnt, s_cut, s_next, s_nk;
    __shared__ unsigned keepw[10];

    hist[tid] = 0;
    if (tid < NW) s_seg[tid] = 0;
    __syncthreads();

    const float4* cls4 = (const float4*)cls;
    const int segBase = wid * WSEG;

    // ---- stream part [i0, i0+p4): filter above floor into per-warp cache ----
    auto proc = [&](float4 v, int i4) {
        float mx = fmaxf(fmaxf(v.x, v.y), fmaxf(v.z, v.w));
        if (mx >= floorVal) {                 // rare
            float xs[4] = {v.x, v.y, v.z, v.w};
            #pragma unroll
            for (int c = 0; c < 4; c++) {
                float x = xs[c];
                if (x >= floorVal) {
                    int p = atomicAdd(&s_seg[wid], 1);
                    if (p < WSEG) { cval[segBase + p] = x; cidx[segBase + p] = i4*4 + c; }
                }
            }
        }
    };
    {
        const int iEnd = i0 + p4;
        int i = i0 + tid;
        for (; i + 7*1024 < iEnd; i += 8*1024) {
            float4 v0 = cls4[i];          float4 v1 = cls4[i + 1024];
            float4 v2 = cls4[i + 2048];   float4 v3 = cls4[i + 3072];
            float4 v4 = cls4[i + 4096];   float4 v5 = cls4[i + 5120];
            float4 v6 = cls4[i + 6144];   float4 v7 = cls4[i + 7168];
            proc(v0, i);        proc(v1, i + 1024);
            proc(v2, i + 2048); proc(v3, i + 3072);
            proc(v4, i + 4096); proc(v5, i + 5120);
            proc(v6, i + 6144); proc(v7, i + 7168);
        }
        for (; i < iEnd; i += 1024) proc(cls4[i], i);
    }
    __syncthreads();

    // warp-count scan (warp 0), overflow detect
    if (tid < 32) {
        int raw = s_seg[tid];
        int sc  = raw > WSEG ? WSEG : raw;
        unsigned ov = __ballot_sync(FULLM, raw > WSEG);
        int incl = sc;
        #pragma unroll
        for (int off = 1; off < 32; off <<= 1) {
            int t2 = __shfl_up_sync(FULLM, incl, off);
            if (lane >= off) incl += t2;
        }
        s_seg[tid]  = sc;
        s_woff[tid] = incl - sc;
        if (tid == 31) s_ccnt = incl;
        if (tid == 0)  s_ovf = (ov != 0);
    }
    __syncthreads();

    // flatten cache via register staging (3 entries/thread)
    {
        float rv[3]; int ri[3], rd[3]; bool rh[3];
        #pragma unroll
        for (int k = 0; k < 3; k++) {
            int t = tid + k*1024;
            int w = t / WSEG, o = t - w*WSEG;
            rh[k] = (o < s_seg[w]);
            rv[k] = rh[k] ? cval[t] : 0.0f;
            ri[k] = rh[k] ? cidx[t] : 0;
            rd[k] = s_woff[w] + o;
        }
        __syncthreads();
        #pragma unroll
        for (int k = 0; k < 3; k++)
            if (rh[k]) { cval[rd[k]] = rv[k]; cidx[rd[k]] = ri[k]; }
        __syncthreads();
    }

    int  ccnt;
    bool cacheOK;

    if (lvl == 0) {
        // ---- stage 1: export candidates to group buffer ----
        const int myc = s_ccnt;
        if (tid == 0) {
            s_base = atomicAdd(&g_gcnt[b], myc);
            if (s_ovf) g_ovf[b] = 1;
        }
        __syncthreads();
        const int base = s_base;
        for (int t = tid; t < myc; t += 1024) {
            int g = base + t;
            if (g < FLATCAP) g_cand[b][g] = make_int2(__float_as_int(cval[t]), cidx[t]);
        }
        __threadfence();
        if (tid == 0) {
            int old = atomicAdd(&g_arrive[b], 1);
            s_last = (old == 3);
        }
        __syncthreads();
        if (!s_last) return;
        __threadfence();

        // ---- stage 2 assembly (last CTA of group) ----
        // RACE FIX: tid 0 stages counters to shared AND resets globals;
        // everyone reads the shared copies after the barrier.
        if (tid == 0) {
            s_gcnt = g_gcnt[b];
            s_govf = g_ovf[b];
            g_gcnt[b] = 0; g_arrive[b] = 0; g_ovf[b] = 0;
        }
        __syncthreads();
        const int gcnt = s_gcnt;
        cacheOK = (!s_govf) && (gcnt <= FLATCAP);
        ccnt = gcnt < FLATCAP ? gcnt : FLATCAP;
        for (int t = tid; t < ccnt; t += 1024) {
            int2 e = g_cand[b][t];
            cval[t] = __int_as_float(e.x);
            cidx[t] = e.y;
        }
        __syncthreads();
    } else {
        ccnt = s_ccnt;
        cacheOK = (s_ovf == 0);
    }

    // ---------------- processing (one CTA per (b,lvl)) ----------------
    const bool vF = (out_size >= 3840);
    unsigned char* vB = (unsigned char*)out + 12800;
    const int slot0 = b*40 + lvl*10;
    {
        int base5 = b*200 + lvl*50;
        if (tid < 50) out[base5 + tid] = 0.0f;
        if (tid >= 64 && tid < 74) {
            int k = tid - 64;
            if (vF) out[3200 + slot0 + k] = 0.0f;
            else    vB[slot0 + k] = 0;
        }
    }

    // histogram (from flat cache, or full global scan if overflowed)
    if (cacheOK) {
        for (int t = tid; t < ccnt; t += 1024) {
            float x = cval[t];
            int bk = (int)(x * LSCALE); bk = bk > NB-1 ? NB-1 : bk;
            atomicAdd(&hist[bk], 1);
        }
    } else {
        for (int i = tid; i < n4full; i += 1024) {
            float4 v = cls4[i];
            float xs[4] = {v.x, v.y, v.z, v.w};
            for (int c = 0; c < 4; c++) {
                float x = xs[c];
                if (x > 0.0f) {
                    int bk = (int)(x * LSCALE); bk = bk > NB-1 ? NB-1 : bk;
                    atomicAdd(&hist[bk], 1);
                }
            }
        }
    }

    auto computeAbove = [&]() -> int {
        __syncthreads();
        int h = hist[tid];
        int v = h;
        #pragma unroll
        for (int off = 1; off < 32; off <<= 1) {
            int t2 = __shfl_down_sync(FULLM, v, off);
            if (lane + off < 32) v += t2;
        }
        if (lane == 0) wtot[wid] = v;
        __syncthreads();
        int tail = 0;
        for (int w = wid + 1; w < 32; w++) tail += wtot[w];
        return (v - h) + tail;
    };

    auto decode_store = [&](float x, int j) {
        int a = j / HW;
        int rem = j - a*HW;
        const float* bp = boxp + ((size_t)(b*9 + a) * 4) * HW + rem;
        float d0 = bp[0], d1 = bp[HW], d2 = bp[2*HW], d3 = bp[3*HW];
        float4 an = ((const float4*)anc)[j];
        float w = an.z - an.x, h = an.w - an.y;
        float cx = an.x + 0.5f*w, cy = an.y + 0.5f*h;
        d0 = fminf(fmaxf(d0, -2.0f), 2.0f);
        d1 = fminf(fmaxf(d1, -2.0f), 2.0f);
        d2 = fminf(fmaxf(d2, -2.0f), 2.0f);
        d3 = fminf(fmaxf(d3, -2.0f), 2.0f);
        float px = cx + d0*w, py = cy + d1*h;
        float pw = w * expf(d2), ph = h * expf(d3);
        float x1 = fminf(fmaxf(px - 0.5f*pw, 0.0f), 1024.0f);
        float y1 = fminf(fmaxf(py - 0.5f*ph, 0.0f), 1024.0f);
        float x2 = fminf(fmaxf(px + 0.5f*pw, 0.0f), 1024.0f);
        float y2 = fminf(fmaxf(py + 0.5f*ph, 0.0f), 1024.0f);
        float bw = x2 - x1, bh = y2 - y1;
        if (bw > 1.0f && bh > 1.0f && bw < 2000.0f && bh < 2000.0f) {
            int pos = atomicAdd(&s_cnt, 1);
            if (pos < CANDCAP) {
                unsigned lo = ((262143u - (unsigned)j) << 13) | (unsigned)pos;
                sKey[pos] = ((unsigned long long)__float_as_uint(x) << 32) | lo;
                candBox[pos] = make_float4(x1, y1, x2, y2);
            }
        }
    };

    // ---- exact band selection loop ----
    bool histFull = !cacheOK;
    int rawTarget = RAW_T0;
    int guard = 0;
    int cnt = 0, cut = 0;
    while (true) {
        if (tid == 0) s_cut = 0;
        int above = computeAbove();
        {
            int cum = above + hist[tid];
            if (cum >= rawTarget && above < rawTarget) s_cut = tid;
        }
        __syncthreads();
        cut = s_cut;

        if (!histFull && cut < flBK) {
            for (int i = tid; i < n4full; i += 1024) {
                float4 v = cls4[i];
                float xs[4] = {v.x, v.y, v.z, v.w};
                for (int c = 0; c < 4; c++) {
                    float x = xs[c];
                    if (x > 0.0f && x < floorVal) {
                        int bk = (int)(x * LSCALE); bk = bk > NB-1 ? NB-1 : bk;
                        atomicAdd(&hist[bk], 1);
                    }
                }
            }
            histFull = true;
            continue;
        }

        if (tid == 0) s_cnt = 0;
        __syncthreads();
        const float cutVal = (float)cut * (1.0f/128.0f);   // exact

        if (cacheOK && cut >= flBK) {
            for (int t = tid; t < ccnt; t += 1024) {
                float x = cval[t];
                if (x >= cutVal) decode_store(x, cidx[t]);
            }
        } else {
            for (int i = tid; i < n4full; i += 1024) {
                float4 v = cls4[i];
                float xs[4] = {v.x, v.y, v.z, v.w};
                for (int c = 0; c < 4; c++) {
                    float x = xs[c];
                    if (x > 0.0f && x >= cutVal) decode_store(x, i*4 + c);
                }
            }
        }
        __syncthreads();
        cnt = s_cnt;
        if (++guard > 8) break;
        if (cnt > CANDCAP) {
            if (rawTarget > KPRE) { rawTarget = KPRE; continue; }
            break;
        }
        if (cnt >= KPRE || cut == 0) break;
        rawTarget += (KPRE - cnt) + 32;
    }

    int scnt = cnt < CANDCAP ? cnt : CANDCAP;
    if (tid >= scnt && tid < SORTN) sKey[tid] = 0ull;
    __syncthreads();

    // ---- bitonic sort descending, 512 elems ----
    {
        unsigned long long key = (tid < SORTN) ? sKey[tid] : 0ull;
        __syncthreads();
        #pragma unroll
        for (int k = 2; k <= SORTN; k <<= 1) {
            bool segDesc = ((tid & k) == 0);
            #pragma unroll
            for (int j = k >> 1; j > 0; j >>= 1) {
                unsigned long long okey;
                if (j >= 32) {
                    if (tid < SORTN) sKey[tid] = key;
                    __syncthreads();
                    okey = (tid < SORTN) ? sKey[tid ^ j] : 0ull;
                    __syncthreads();
                } else {
                    unsigned hi = __shfl_xor_sync(FULLM, (unsigned)(key >> 32), j);
                    unsigned lo = __shfl_xor_sync(FULLM, (unsigned)key, j);
                    okey = ((unsigned long long)hi << 32) | lo;
                }
                bool keepMax = (((tid & j) == 0) == segDesc);
                bool take = keepMax ? (okey > key) : (okey < key);
                if (tid < SORTN && take) key = okey;
            }
        }
        if (tid < SORTN) sKey[tid] = key;
        __syncthreads();
    }

    // ---- NMS ----
    const int m = scnt < KPRE ? scnt : KPRE;
    float mx1 = 0, my1 = 0, mx2 = 0, my2 = 0, mar = 0;
    if (tid < m) {
        unsigned long long kk = sKey[tid];
        float4 bb = candBox[(int)(kk & 0x1FFFu)];
        mx1 = bb.x; my1 = bb.y; mx2 = bb.z; my2 = bb.w;
        mar = (bb.z - bb.x) * (bb.w - bb.y);
    }
    if (tid < 10) {
        int lo = tid * 32;
        unsigned w;
        if (m >= lo + 32) w = FULLM;
        else if (m > lo)  w = (1u << (m - lo)) - 1u;
        else              w = 0u;
        keepw[tid] = w;
    }
    if (tid == 0) s_nk = 0;
    __syncthreads();

    for (int round = 0; round <= KOUT; round++) {
        if (tid < 32) {
            unsigned v = (tid < 10) ? keepw[tid] : 0u;
            unsigned nz = __ballot_sync(FULLM, v != 0u);
            int w = __ffs(nz) - 1;
            unsigned vw = __shfl_sync(FULLM, v, (w < 0) ? 0 : w);
            if (tid == 0) s_next = nz ? (w*32 + __ffs(vw) - 1) : -1;
        }
        __syncthreads();
        int i = s_next;
        if (i < 0 || s_nk >= KOUT) break;

        unsigned long long ki = sKey[i];
        float4 bi = candBox[(int)(ki & 0x1FFFu)];
        float ba = (bi.z - bi.x) * (bi.w - bi.y);

        if (tid == 0) {
            int nk = s_nk;
            float logit = __uint_as_float((unsigned)(ki >> 32));
            float sc = 1.0f / (1.0f + expf(-logit));
            int s5 = b*200 + (lvl*10 + nk)*5;
            out[s5+0] = bi.x; out[s5+1] = bi.y;
            out[s5+2] = bi.z; out[s5+3] = bi.w;
            out[s5+4] = sc;
            if (vF) out[3200 + slot0 + nk] = 1.0f;
            else    vB[slot0 + nk] = 1;
            s_nk = nk + 1;
            atomicAnd(&keepw[i >> 5], ~(1u << (i & 31)));
        }
        if (tid > i && tid < m && ((keepw[tid >> 5] >> (tid & 31)) & 1u)) {
            float ix1 = fmaxf(bi.x, mx1), iy1 = fmaxf(bi.y, my1);
            float ix2 = fminf(bi.z, mx2), iy2 = fminf(bi.w, my2);
            float iw = fmaxf(ix2 - ix1, 0.0f), ih = fmaxf(iy2 - iy1, 0.0f);
            float inter = iw * ih;
            float iou = inter / (ba + mar - inter + 1e-9f);
            if (iou > 0.3f) atomicAnd(&keepw[tid >> 5], ~(1u << (tid & 31)));
        }
        __syncthreads();
    }
}

// ---------------------------------------------------------------------------
extern "C" void kernel_launch(void* const* d_in, const int* in_sizes, int n_in,
                              void* d_out, int out_size) {
    Ptrs P;
    if (n_in >= 2 && in_sizes[0] == 2359296 && in_sizes[1] == 9437184) {
        for (int l = 0; l < 4; l++) {
            P.cls[l] = (const float*)d_in[3*l + 0];
            P.box[l] = (const float*)d_in[3*l + 1];
            P.anc[l] = (const float*)d_in[3*l + 2];
        }
    } else if (n_in >= 1 && in_sizes[0] == 2359296) {
        for (int l = 0; l < 4; l++) {
            P.cls[l] = (const float*)d_in[l];
            P.box[l] = (const float*)d_in[4 + l];
            P.anc[l] = (const float*)d_in[8 + l];
        }
    } else {
        for (int l = 0; l < 4; l++) {
            P.anc[l] = (const float*)d_in[l];
            P.box[l] = (const float*)d_in[4 + l];
            P.cls[l] = (const float*)d_in[8 + l];
        }
    }
    detect_kernel<<<112, 1024>>>(P, (float*)d_out, out_size);
}

// round 14
// speedup vs baseline: 1.0094x; 1.0094x over previous
#include <cuda_runtime.h>
#include <math.h>

#define NB       1024
#define LSCALE   128.0f
#define KPRE     300
#define KOUT     10
#define SORTN    512
#define CANDCAP  512
#define NW       32
#define WSEG     96
#define RAW_T0   340
#define FULLM    0xFFFFFFFFu

struct Ptrs {
    const float* cls[4];
    const float* box[4];
    const float* anc[4];
};

// One CTA per (batch,level). Stream cls with a tuned per-level floor into
// per-warp smem caches. FAST PATH: decode every cached entry; if the valid
// count lands in [300, 512] the cache is provably a top-300-valid superset
// (floor is a pure score threshold) -> sort 512 (key = score|~ancidx|slot,
// preserving lax.top_k tie order) -> register NMS. FALLBACK (cache overflow /
// count out of range): exact histogram + band selection over global data.
__global__ __launch_bounds__(1024) void detect_kernel(Ptrs P, float* out, int out_size) {
    const int img = blockIdx.x;
    const int b   = img >> 2;
    const int lvl = img & 3;
    const int HW  = 16384 >> (2*lvl);
    const int N   = 9 * HW;
    const int flBK = (lvl==0) ? 354 : (lvl==1) ? 291 : (lvl==2) ? 215 : 114;
    const float floorVal = (float)flBK * (1.0f/128.0f);   // exact
    const float* cls  = P.cls[lvl] + (size_t)b * N;
    const float* boxp = P.box[lvl];
    const float* anc  = P.anc[lvl];
    const int tid = threadIdx.x, wid = tid >> 5, lane = tid & 31;

    __shared__ int   hist[NB];
    __shared__ float cval[NW*WSEG];
    __shared__ int   cidx[NW*WSEG];
    __shared__ unsigned long long sKey[SORTN];
    __shared__ float4 candBox[CANDCAP];
    __shared__ int   wtot[32];
    __shared__ int   s_seg[NW];
    __shared__ unsigned s_flags;
    __shared__ int   s_cnt, s_cut, s_next, s_nk;
    __shared__ unsigned keepw[10];

    const bool vF = (out_size >= 3840);
    unsigned char* vB = (unsigned char*)out + 12800;
    const int slot0 = b*40 + lvl*10;

    // zero this CTA's output region (d_out is poisoned)
    {
        int base5 = b*200 + lvl*50;
        if (tid < 50) out[base5 + tid] = 0.0f;
        if (tid >= 64 && tid < 74) {
            int k = tid - 64;
            if (vF) out[3200 + slot0 + k] = 0.0f;
            else    vB[slot0 + k] = 0;
        }
    }
    if (tid < NW) s_seg[tid] = 0;
    if (tid == 0) s_cnt = 0;
    __syncthreads();

    const int n4 = N >> 2;
    const float4* cls4 = (const float4*)cls;
    const int segBase = wid * WSEG;

    // ---- stream: filter above floor into per-warp cache ----
    auto proc = [&](float4 v, int i4) {
        float mx = fmaxf(fmaxf(v.x, v.y), fmaxf(v.z, v.w));
        if (mx >= floorVal) {                 // rare
            float xs[4] = {v.x, v.y, v.z, v.w};
            #pragma unroll
            for (int c = 0; c < 4; c++) {
                float x = xs[c];
                if (x >= floorVal) {
                    int p = atomicAdd(&s_seg[wid], 1);
                    if (p < WSEG) { cval[segBase + p] = x; cidx[segBase + p] = i4*4 + c; }
                }
            }
        }
    };
    {
        int i = tid;
        for (; i + 7*1024 < n4; i += 8*1024) {
            float4 v0 = cls4[i];          float4 v1 = cls4[i + 1024];
            float4 v2 = cls4[i + 2048];   float4 v3 = cls4[i + 3072];
            float4 v4 = cls4[i + 4096];   float4 v5 = cls4[i + 5120];
            float4 v6 = cls4[i + 6144];   float4 v7 = cls4[i + 7168];
            proc(v0, i);        proc(v1, i + 1024);
            proc(v2, i + 2048); proc(v3, i + 3072);
            proc(v4, i + 4096); proc(v5, i + 5120);
            proc(v6, i + 6144); proc(v7, i + 7168);
        }
        for (; i < n4; i += 1024) proc(cls4[i], i);
    }
    __syncthreads();

    if (tid < 32) {
        unsigned bad = __ballot_sync(FULLM, s_seg[tid] > WSEG);
        if (tid == 0) s_flags = bad;
    }
    __syncthreads();
    const bool cacheOK = (s_flags == 0);

    auto decode_store = [&](float x, int j) {
        int a = j / HW;
        int rem = j - a*HW;
        const float* bp = boxp + ((size_t)(b*9 + a) * 4) * HW + rem;
        float d0 = bp[0], d1 = bp[HW], d2 = bp[2*HW], d3 = bp[3*HW];
        float4 an = ((const float4*)anc)[j];
        float w = an.z - an.x, h = an.w - an.y;
        float cx = an.x + 0.5f*w, cy = an.y + 0.5f*h;
        d0 = fminf(fmaxf(d0, -2.0f), 2.0f);
        d1 = fminf(fmaxf(d1, -2.0f), 2.0f);
        d2 = fminf(fmaxf(d2, -2.0f), 2.0f);
        d3 = fminf(fmaxf(d3, -2.0f), 2.0f);
        float px = cx + d0*w, py = cy + d1*h;
        float pw = w * expf(d2), ph = h * expf(d3);
        float x1 = fminf(fmaxf(px - 0.5f*pw, 0.0f), 1024.0f);
        float y1 = fminf(fmaxf(py - 0.5f*ph, 0.0f), 1024.0f);
        float x2 = fminf(fmaxf(px + 0.5f*pw, 0.0f), 1024.0f);
        float y2 = fminf(fmaxf(py + 0.5f*ph, 0.0f), 1024.0f);
        float bw = x2 - x1, bh = y2 - y1;
        if (bw > 1.0f && bh > 1.0f && bw < 2000.0f && bh < 2000.0f) {
            int pos = atomicAdd(&s_cnt, 1);
            if (pos < CANDCAP) {
                unsigned lo = ((262143u - (unsigned)j) << 13) | (unsigned)pos;
                sKey[pos] = ((unsigned long long)__float_as_uint(x) << 32) | lo;
                candBox[pos] = make_float4(x1, y1, x2, y2);
            }
        }
    };

    // ---- FAST PATH: decode everything above the floor ----
    int cnt = 0;
    bool done = false;
    if (cacheOK) {
        for (int t = tid; t < NW*WSEG; t += 1024) {
            int w = t / WSEG, o = t - w*WSEG;
            if (o < s_seg[w]) decode_store(cval[t], cidx[t]);
        }
        __syncthreads();
        cnt = s_cnt;
        done = (cnt >= KPRE && cnt <= CANDCAP);
    }

    // ---- FALLBACK: exact histogram + band selection over global data ----
    if (!done) {
        hist[tid] = 0;
        __syncthreads();
        for (int i = tid; i < n4; i += 1024) {
            float4 v = cls4[i];
            float xs[4] = {v.x, v.y, v.z, v.w};
            for (int c = 0; c < 4; c++) {
                float x = xs[c];
                if (x > 0.0f) {
                    int bk = (int)(x * LSCALE); bk = bk > NB-1 ? NB-1 : bk;
                    atomicAdd(&hist[bk], 1);
                }
            }
        }

        auto computeAbove = [&]() -> int {
            __syncthreads();
            int h = hist[tid];
            int v = h;
            #pragma unroll
            for (int off = 1; off < 32; off <<= 1) {
                int t2 = __shfl_down_sync(FULLM, v, off);
                if (lane + off < 32) v += t2;
            }
            if (lane == 0) wtot[wid] = v;
            __syncthreads();
            int tail = 0;
            for (int w = wid + 1; w < 32; w++) tail += wtot[w];
            return (v - h) + tail;
        };

        int rawTarget = RAW_T0;
        int guard = 0;
        while (true) {
            if (tid == 0) s_cut = 0;
            int above = computeAbove();
            {
                int cum = above + hist[tid];
                if (cum >= rawTarget && above < rawTarget) s_cut = tid;
            }
            __syncthreads();
            int cut = s_cut;

            if (tid == 0) s_cnt = 0;
            __syncthreads();
            const float cutVal = (float)cut * (1.0f/128.0f);   // exact

            for (int i = tid; i < n4; i += 1024) {
                float4 v = cls4[i];
                float xs[4] = {v.x, v.y, v.z, v.w};
                for (int c = 0; c < 4; c++) {
                    float x = xs[c];
                    if (x > 0.0f && x >= cutVal) decode_store(x, i*4 + c);
                }
            }
            __syncthreads();
            cnt = s_cnt;
            if (++guard > 8) break;
            if (cnt > CANDCAP) {
                if (rawTarget > KPRE) { rawTarget = KPRE; continue; }
                break;
            }
            if (cnt >= KPRE || cut == 0) break;
            rawTarget += (KPRE - cnt) + 32;
        }
    }

    int scnt = cnt < CANDCAP ? cnt : CANDCAP;
    if (tid >= scnt && tid < SORTN) sKey[tid] = 0ull;
    __syncthreads();

    // ---- bitonic sort descending, 512 elems ----
    {
        unsigned long long key = (tid < SORTN) ? sKey[tid] : 0ull;
        __syncthreads();
        #pragma unroll
        for (int k = 2; k <= SORTN; k <<= 1) {
            bool segDesc = ((tid & k) == 0);
            #pragma unroll
            for (int j = k >> 1; j > 0; j >>= 1) {
                unsigned long long okey;
                if (j >= 32) {
                    if (tid < SORTN) sKey[tid] = key;
                    __syncthreads();
                    okey = (tid < SORTN) ? sKey[tid ^ j] : 0ull;
                    __syncthreads();
                } else {
                    unsigned hi = __shfl_xor_sync(FULLM, (unsigned)(key >> 32), j);
                    unsigned lo = __shfl_xor_sync(FULLM, (unsigned)key, j);
                    okey = ((unsigned long long)hi << 32) | lo;
                }
                bool keepMax = (((tid & j) == 0) == segDesc);
                bool take = keepMax ? (okey > key) : (okey < key);
                if (tid < SORTN && take) key = okey;
            }
        }
        if (tid < SORTN) sKey[tid] = key;
        __syncthreads();
    }

    // ---- NMS: each thread holds its candidate's box in registers ----
    const int m = scnt < KPRE ? scnt : KPRE;
    float mx1 = 0, my1 = 0, mx2 = 0, my2 = 0, mar = 0;
    if (tid < m) {
        unsigned long long kk = sKey[tid];
        float4 bb = candBox[(int)(kk & 0x1FFFu)];
        mx1 = bb.x; my1 = bb.y; mx2 = bb.z; my2 = bb.w;
        mar = (bb.z - bb.x) * (bb.w - bb.y);
    }
    if (tid < 10) {
        int lo = tid * 32;
        unsigned w;
        if (m >= lo + 32) w = FULLM;
        else if (m > lo)  w = (1u << (m - lo)) - 1u;
        else              w = 0u;
        keepw[tid] = w;
    }
    if (tid == 0) s_nk = 0;
    __syncthreads();

    for (int round = 0; round <= KOUT; round++) {
        if (tid < 32) {
            unsigned v = (tid < 10) ? keepw[tid] : 0u;
            unsigned nz = __ballot_sync(FULLM, v != 0u);
            int w = __ffs(nz) - 1;
            unsigned vw = __shfl_sync(FULLM, v, (w < 0) ? 0 : w);
            if (tid == 0) s_next = nz ? (w*32 + __ffs(vw) - 1) : -1;
        }
        __syncthreads();
        int i = s_next;
        if (i < 0 || s_nk >= KOUT) break;

        unsigned long long ki = sKey[i];               // broadcast
        float4 bi = candBox[(int)(ki & 0x1FFFu)];      // broadcast
        float ba = (bi.z - bi.x) * (bi.w - bi.y);

        if (tid == 0) {
            int nk = s_nk;
            float logit = __uint_as_float((unsigned)(ki >> 32));
            float sc = 1.0f / (1.0f + expf(-logit));
            int s5 = b*200 + (lvl*10 + nk)*5;
            out[s5+0] = bi.x; out[s5+1] = bi.y;
            out[s5+2] = bi.z; out[s5+3] = bi.w;
            out[s5+4] = sc;
            if (vF) out[3200 + slot0 + nk] = 1.0f;
            else    vB[slot0 + nk] = 1;
            s_nk = nk + 1;
            atomicAnd(&keepw[i >> 5], ~(1u << (i & 31)));
        }
        if (tid > i && tid < m && ((keepw[tid >> 5] >> (tid & 31)) & 1u)) {
            float ix1 = fmaxf(bi.x, mx1), iy1 = fmaxf(bi.y, my1);
            float ix2 = fminf(bi.z, mx2), iy2 = fminf(bi.w, my2);
            float iw = fmaxf(ix2 - ix1, 0.0f), ih = fmaxf(iy2 - iy1, 0.0f);
            float inter = iw * ih;
            float iou = inter / (ba + mar - inter + 1e-9f);
            if (iou > 0.3f) atomicAnd(&keepw[tid >> 5], ~(1u << (tid & 31)));
        }
        __syncthreads();
    }
}

// ---------------------------------------------------------------------------
extern "C" void kernel_launch(void* const* d_in, const int* in_sizes, int n_in,
                              void* d_out, int out_size) {
    Ptrs P;
    if (n_in >= 2 && in_sizes[0] == 2359296 && in_sizes[1] == 9437184) {
        for (int l = 0; l < 4; l++) {
            P.cls[l] = (const float*)d_in[3*l + 0];
            P.box[l] = (const float*)d_in[3*l + 1];
            P.anc[l] = (const float*)d_in[3*l + 2];
        }
    } else if (n_in >= 1 && in_sizes[0] == 2359296) {
        for (int l = 0; l < 4; l++) {
            P.cls[l] = (const float*)d_in[l];
            P.box[l] = (const float*)d_in[4 + l];
            P.anc[l] = (const float*)d_in[8 + l];
        }
    } else {
        for (int l = 0; l < 4; l++) {
            P.anc[l] = (const float*)d_in[l];
            P.box[l] = (const float*)d_in[4 + l];
            P.cls[l] = (const float*)d_in[8 + l];
        }
    }
    detect_kernel<<<64, 1024>>>(P, (float*)d_out, out_size);
}

// round 15
// speedup vs baseline: 1.6518x; 1.6365x over previous
#include <cuda_runtime.h>
#include <math.h>

#define NB       1024
#define LSCALE   128.0f
#define KPRE     300
#define KOUT     10
#define SORTN    512
#define CANDCAP  512
#define NW       32
#define WSEG     96
#define RAW_T0   340
#define FULLM    0xFFFFFFFFu

struct Ptrs {
    const float* cls[4];
    const float* box[4];
    const float* anc[4];
};

// One CTA per (batch,level). Stream cls with a tuned per-level floor into
// per-warp smem caches. FAST PATH: decode every cached entry; if the valid
// count lands in [300, 512] the cache is provably a top-300-valid superset
// -> sort -> NMS. FALLBACK: exact histogram + band selection, built FROM THE
// CACHE whenever possible (global data touched only on cache overflow or a
// cut below the floor). Never costs more than one extra cache pass + hist.
__global__ __launch_bounds__(1024) void detect_kernel(Ptrs P, float* out, int out_size) {
    const int img = blockIdx.x;
    const int b   = img >> 2;
    const int lvl = img & 3;
    const int HW  = 16384 >> (2*lvl);
    const int N   = 9 * HW;
    const int flBK = (lvl==0) ? 354 : (lvl==1) ? 291 : (lvl==2) ? 215 : 114;
    const float floorVal = (float)flBK * (1.0f/128.0f);   // exact
    const float* cls  = P.cls[lvl] + (size_t)b * N;
    const float* boxp = P.box[lvl];
    const float* anc  = P.anc[lvl];
    const int tid = threadIdx.x, wid = tid >> 5, lane = tid & 31;

    __shared__ int   hist[NB];
    __shared__ float cval[NW*WSEG];
    __shared__ int   cidx[NW*WSEG];
    __shared__ unsigned long long sKey[SORTN];
    __shared__ float4 candBox[CANDCAP];
    __shared__ int   wtot[32];
    __shared__ int   s_seg[NW];
    __shared__ unsigned s_flags;
    __shared__ int   s_cnt, s_cut, s_next, s_nk;
    __shared__ unsigned keepw[10];

    const bool vF = (out_size >= 3840);
    unsigned char* vB = (unsigned char*)out + 12800;
    const int slot0 = b*40 + lvl*10;

    // zero this CTA's output region (d_out is poisoned)
    {
        int base5 = b*200 + lvl*50;
        if (tid < 50) out[base5 + tid] = 0.0f;
        if (tid >= 64 && tid < 74) {
            int k = tid - 64;
            if (vF) out[3200 + slot0 + k] = 0.0f;
            else    vB[slot0 + k] = 0;
        }
    }
    if (tid < NW) s_seg[tid] = 0;
    if (tid == 0) s_cnt = 0;
    __syncthreads();

    const int n4 = N >> 2;
    const float4* cls4 = (const float4*)cls;
    const int segBase = wid * WSEG;

    // ---- stream: filter above floor into per-warp cache ----
    auto proc = [&](float4 v, int i4) {
        float mx = fmaxf(fmaxf(v.x, v.y), fmaxf(v.z, v.w));
        if (mx >= floorVal) {                 // rare
            float xs[4] = {v.x, v.y, v.z, v.w};
            #pragma unroll
            for (int c = 0; c < 4; c++) {
                float x = xs[c];
                if (x >= floorVal) {
                    int p = atomicAdd(&s_seg[wid], 1);
                    if (p < WSEG) { cval[segBase + p] = x; cidx[segBase + p] = i4*4 + c; }
                }
            }
        }
    };
    {
        int i = tid;
        for (; i + 7*1024 < n4; i += 8*1024) {
            float4 v0 = cls4[i];          float4 v1 = cls4[i + 1024];
            float4 v2 = cls4[i + 2048];   float4 v3 = cls4[i + 3072];
            float4 v4 = cls4[i + 4096];   float4 v5 = cls4[i + 5120];
            float4 v6 = cls4[i + 6144];   float4 v7 = cls4[i + 7168];
            proc(v0, i);        proc(v1, i + 1024);
            proc(v2, i + 2048); proc(v3, i + 3072);
            proc(v4, i + 4096); proc(v5, i + 5120);
            proc(v6, i + 6144); proc(v7, i + 7168);
        }
        for (; i < n4; i += 1024) proc(cls4[i], i);
    }
    __syncthreads();

    if (tid < 32) {
        unsigned bad = __ballot_sync(FULLM, s_seg[tid] > WSEG);
        if (tid == 0) s_flags = bad;
    }
    __syncthreads();
    const bool cacheOK = (s_flags == 0);

    auto decode_store = [&](float x, int j) {
        int a = j / HW;
        int rem = j - a*HW;
        const float* bp = boxp + ((size_t)(b*9 + a) * 4) * HW + rem;
        float d0 = bp[0], d1 = bp[HW], d2 = bp[2*HW], d3 = bp[3*HW];
        float4 an = ((const float4*)anc)[j];
        float w = an.z - an.x, h = an.w - an.y;
        float cx = an.x + 0.5f*w, cy = an.y + 0.5f*h;
        d0 = fminf(fmaxf(d0, -2.0f), 2.0f);
        d1 = fminf(fmaxf(d1, -2.0f), 2.0f);
        d2 = fminf(fmaxf(d2, -2.0f), 2.0f);
        d3 = fminf(fmaxf(d3, -2.0f), 2.0f);
        float px = cx + d0*w, py = cy + d1*h;
        float pw = w * expf(d2), ph = h * expf(d3);
        float x1 = fminf(fmaxf(px - 0.5f*pw, 0.0f), 1024.0f);
        float y1 = fminf(fmaxf(py - 0.5f*ph, 0.0f), 1024.0f);
        float x2 = fminf(fmaxf(px + 0.5f*pw, 0.0f), 1024.0f);
        float y2 = fminf(fmaxf(py + 0.5f*ph, 0.0f), 1024.0f);
        float bw = x2 - x1, bh = y2 - y1;
        if (bw > 1.0f && bh > 1.0f && bw < 2000.0f && bh < 2000.0f) {
            int pos = atomicAdd(&s_cnt, 1);
            if (pos < CANDCAP) {
                unsigned lo = ((262143u - (unsigned)j) << 13) | (unsigned)pos;
                sKey[pos] = ((unsigned long long)__float_as_uint(x) << 32) | lo;
                candBox[pos] = make_float4(x1, y1, x2, y2);
            }
        }
    };

    // ---- FAST PATH: decode everything above the floor ----
    int cnt = 0;
    bool done = false;
    if (cacheOK) {
        for (int t = tid; t < NW*WSEG; t += 1024) {
            int w = t / WSEG, o = t - w*WSEG;
            if (o < s_seg[w]) decode_store(cval[t], cidx[t]);
        }
        __syncthreads();
        cnt = s_cnt;
        done = (cnt >= KPRE && cnt <= CANDCAP);
    }

    // ---- FALLBACK: exact hist + band selection, cache-based when possible ----
    if (!done) {
        hist[tid] = 0;
        __syncthreads();
        if (cacheOK) {
            // histogram from cache (covers x >= floorVal only)
            for (int t = tid; t < NW*WSEG; t += 1024) {
                int w = t / WSEG, o = t - w*WSEG;
                if (o < s_seg[w]) {
                    float x = cval[t];
                    int bk = (int)(x * LSCALE); bk = bk > NB-1 ? NB-1 : bk;
                    atomicAdd(&hist[bk], 1);
                }
            }
        } else {
            for (int i = tid; i < n4; i += 1024) {
                float4 v = cls4[i];
                float xs[4] = {v.x, v.y, v.z, v.w};
                for (int c = 0; c < 4; c++) {
                    float x = xs[c];
                    if (x > 0.0f) {
                        int bk = (int)(x * LSCALE); bk = bk > NB-1 ? NB-1 : bk;
                        atomicAdd(&hist[bk], 1);
                    }
                }
            }
        }

        auto computeAbove = [&]() -> int {
            __syncthreads();
            int h = hist[tid];
            int v = h;
            #pragma unroll
            for (int off = 1; off < 32; off <<= 1) {
                int t2 = __shfl_down_sync(FULLM, v, off);
                if (lane + off < 32) v += t2;
            }
            if (lane == 0) wtot[wid] = v;
            __syncthreads();
            int tail = 0;
            for (int w = wid + 1; w < 32; w++) tail += wtot[w];
            return (v - h) + tail;
        };

        bool histFull = !cacheOK;    // cache hist lacks the below-floor part
        int rawTarget = RAW_T0;
        int guard = 0;
        while (true) {
            if (tid == 0) s_cut = 0;
            int above = computeAbove();
            {
                int cum = above + hist[tid];
                if (cum >= rawTarget && above < rawTarget) s_cut = tid;
            }
            __syncthreads();
            int cut = s_cut;

            if (!histFull && cut < flBK) {
                // cold: extend histogram below the floor from global (rare)
                for (int i = tid; i < n4; i += 1024) {
                    float4 v = cls4[i];
                    float xs[4] = {v.x, v.y, v.z, v.w};
                    for (int c = 0; c < 4; c++) {
                        float x = xs[c];
                        if (x > 0.0f && x < floorVal) {
                            int bk = (int)(x * LSCALE); bk = bk > NB-1 ? NB-1 : bk;
                            atomicAdd(&hist[bk], 1);
                        }
                    }
                }
                histFull = true;
                continue;
            }

            if (tid == 0) s_cnt = 0;
            __syncthreads();
            const float cutVal = (float)cut * (1.0f/128.0f);   // exact

            if (cacheOK && cut >= flBK) {
                // band decode from cache
                for (int t = tid; t < NW*WSEG; t += 1024) {
                    int w = t / WSEG, o = t - w*WSEG;
                    if (o < s_seg[w]) {
                        float x = cval[t];
                        if (x >= cutVal) decode_store(x, cidx[t]);
                    }
                }
            } else {
                // band decode from global (overflow or cut below floor)
                for (int i = tid; i < n4; i += 1024) {
                    float4 v = cls4[i];
                    float xs[4] = {v.x, v.y, v.z, v.w};
                    for (int c = 0; c < 4; c++) {
                        float x = xs[c];
                        if (x > 0.0f && x >= cutVal) decode_store(x, i*4 + c);
                    }
                }
            }
            __syncthreads();
            cnt = s_cnt;
            if (++guard > 8) break;
            if (cnt > CANDCAP) {
                if (rawTarget > KPRE) { rawTarget = KPRE; continue; }
                break;
            }
            if (cnt >= KPRE || cut == 0) break;
            rawTarget += (KPRE - cnt) + 32;
        }
    }

    int scnt = cnt < CANDCAP ? cnt : CANDCAP;
    if (tid >= scnt && tid < SORTN) sKey[tid] = 0ull;
    __syncthreads();

    // ---- bitonic sort descending, 512 elems ----
    {
        unsigned long long key = (tid < SORTN) ? sKey[tid] : 0ull;
        __syncthreads();
        #pragma unroll
        for (int k = 2; k <= SORTN; k <<= 1) {
            bool segDesc = ((tid & k) == 0);
            #pragma unroll
            for (int j = k >> 1; j > 0; j >>= 1) {
                unsigned long long okey;
                if (j >= 32) {
                    if (tid < SORTN) sKey[tid] = key;
                    __syncthreads();
                    okey = (tid < SORTN) ? sKey[tid ^ j] : 0ull;
                    __syncthreads();
                } else {
                    unsigned hi = __shfl_xor_sync(FULLM, (unsigned)(key >> 32), j);
                    unsigned lo = __shfl_xor_sync(FULLM, (unsigned)key, j);
                    okey = ((unsigned long long)hi << 32) | lo;
                }
                bool keepMax = (((tid & j) == 0) == segDesc);
                bool take = keepMax ? (okey > key) : (okey < key);
                if (tid < SORTN && take) key = okey;
            }
        }
        if (tid < SORTN) sKey[tid] = key;
        __syncthreads();
    }

    // ---- NMS: each thread holds its candidate's box in registers ----
    const int m = scnt < KPRE ? scnt : KPRE;
    float mx1 = 0, my1 = 0, mx2 = 0, my2 = 0, mar = 0;
    if (tid < m) {
        unsigned long long kk = sKey[tid];
        float4 bb = candBox[(int)(kk & 0x1FFFu)];
        mx1 = bb.x; my1 = bb.y; mx2 = bb.z; my2 = bb.w;
        mar = (bb.z - bb.x) * (bb.w - bb.y);
    }
    if (tid < 10) {
        int lo = tid * 32;
        unsigned w;
        if (m >= lo + 32) w = FULLM;
        else if (m > lo)  w = (1u << (m - lo)) - 1u;
        else              w = 0u;
        keepw[tid] = w;
    }
    if (tid == 0) s_nk = 0;
    __syncthreads();

    for (int round = 0; round <= KOUT; round++) {
        if (tid < 32) {
            unsigned v = (tid < 10) ? keepw[tid] : 0u;
            unsigned nz = __ballot_sync(FULLM, v != 0u);
            int w = __ffs(nz) - 1;
            unsigned vw = __shfl_sync(FULLM, v, (w < 0) ? 0 : w);
            if (tid == 0) s_next = nz ? (w*32 + __ffs(vw) - 1) : -1;
        }
        __syncthreads();
        int i = s_next;
        if (i < 0 || s_nk >= KOUT) break;

        unsigned long long ki = sKey[i];               // broadcast
        float4 bi = candBox[(int)(ki & 0x1FFFu)];      // broadcast
        float ba = (bi.z - bi.x) * (bi.w - bi.y);

        if (tid == 0) {
            int nk = s_nk;
            float logit = __uint_as_float((unsigned)(ki >> 32));
            float sc = 1.0f / (1.0f + expf(-logit));
            int s5 = b*200 + (lvl*10 + nk)*5;
            out[s5+0] = bi.x; out[s5+1] = bi.y;
            out[s5+2] = bi.z; out[s5+3] = bi.w;
            out[s5+4] = sc;
            if (vF) out[3200 + slot0 + nk] = 1.0f;
            else    vB[slot0 + nk] = 1;
            s_nk = nk + 1;
            atomicAnd(&keepw[i >> 5], ~(1u << (i & 31)));
        }
        if (tid > i && tid < m && ((keepw[tid >> 5] >> (tid & 31)) & 1u)) {
            float ix1 = fmaxf(bi.x, mx1), iy1 = fmaxf(bi.y, my1);
            float ix2 = fminf(bi.z, mx2), iy2 = fminf(bi.w, my2);
            float iw = fmaxf(ix2 - ix1, 0.0f), ih = fmaxf(iy2 - iy1, 0.0f);
            float inter = iw * ih;
            float iou = inter / (ba + mar - inter + 1e-9f);
            if (iou > 0.3f) atomicAnd(&keepw[tid >> 5], ~(1u << (tid & 31)));
        }
        __syncthreads();
    }
}

// ---------------------------------------------------------------------------
extern "C" void kernel_launch(void* const* d_in, const int* in_sizes, int n_in,
                              void* d_out, int out_size) {
    Ptrs P;
    if (n_in >= 2 && in_sizes[0] == 2359296 && in_sizes[1] == 9437184) {
        for (int l = 0; l < 4; l++) {
            P.cls[l] = (const float*)d_in[3*l + 0];
            P.box[l] = (const float*)d_in[3*l + 1];
            P.anc[l] = (const float*)d_in[3*l + 2];
        }
    } else if (n_in >= 1 && in_sizes[0] == 2359296) {
        for (int l = 0; l < 4; l++) {
            P.cls[l] = (const float*)d_in[l];
            P.box[l] = (const float*)d_in[4 + l];
            P.anc[l] = (const float*)d_in[8 + l];
        }
    } else {
        for (int l = 0; l < 4; l++) {
            P.anc[l] = (const float*)d_in[l];
            P.box[l] = (const float*)d_in[4 + l];
            P.cls[l] = (const float*)d_in[8 + l];
        }
    }
    detect_kernel<<<64, 1024>>>(P, (float*)d_out, out_size);
}

// round 16
// speedup vs baseline: 1.7788x; 1.0769x over previous
#include <cuda_runtime.h>
#include <math.h>

#define NB       1024
#define LSCALE   128.0f
#define KPRE     300
#define KOUT     10
#define SORTN    512
#define CANDCAP  512
#define NW       32
#define WSEG     96
#define RAW_T0   340
#define FULLM    0xFFFFFFFFu

struct Ptrs {
    const float* cls[4];
    const float* box[4];
    const float* anc[4];
};

// One CTA per (batch,level). Stream cls with a tuned per-level floor into
// per-warp smem caches. FAST PATH: decode every cached entry; if the valid
// count lands in [300, 512] the cache is provably a top-300-valid superset
// -> sort -> NMS. FALLBACK: exact histogram + band selection, built FROM THE
// CACHE whenever possible. After candidate collection the upper 512 threads
// retire (exited threads don't count toward bar.sync), halving the barrier
// cost of the sort + NMS phases which only use 512 threads.
__global__ __launch_bounds__(1024) void detect_kernel(Ptrs P, float* out, int out_size) {
    const int img = blockIdx.x;
    const int b   = img >> 2;
    const int lvl = img & 3;
    const int HW  = 16384 >> (2*lvl);
    const int N   = 9 * HW;
    const int flBK = (lvl==0) ? 354 : (lvl==1) ? 291 : (lvl==2) ? 215 : 114;
    const float floorVal = (float)flBK * (1.0f/128.0f);   // exact
    const float* cls  = P.cls[lvl] + (size_t)b * N;
    const float* boxp = P.box[lvl];
    const float* anc  = P.anc[lvl];
    const int tid = threadIdx.x, wid = tid >> 5, lane = tid & 31;

    __shared__ int   hist[NB];
    __shared__ float cval[NW*WSEG];
    __shared__ int   cidx[NW*WSEG];
    __shared__ unsigned long long sKey[SORTN];
    __shared__ float4 candBox[CANDCAP];
    __shared__ int   wtot[32];
    __shared__ int   s_seg[NW];
    __shared__ unsigned s_flags;
    __shared__ int   s_cnt, s_cut, s_next, s_nk;
    __shared__ unsigned keepw[10];

    const bool vF = (out_size >= 3840);
    unsigned char* vB = (unsigned char*)out + 12800;
    const int slot0 = b*40 + lvl*10;

    // zero this CTA's output region (d_out is poisoned)
    {
        int base5 = b*200 + lvl*50;
        if (tid < 50) out[base5 + tid] = 0.0f;
        if (tid >= 64 && tid < 74) {
            int k = tid - 64;
            if (vF) out[3200 + slot0 + k] = 0.0f;
            else    vB[slot0 + k] = 0;
        }
    }
    if (tid < NW) s_seg[tid] = 0;
    if (tid == 0) s_cnt = 0;
    __syncthreads();

    const int n4 = N >> 2;
    const float4* cls4 = (const float4*)cls;
    const int segBase = wid * WSEG;

    // ---- stream: filter above floor into per-warp cache ----
    auto proc = [&](float4 v, int i4) {
        float mx = fmaxf(fmaxf(v.x, v.y), fmaxf(v.z, v.w));
        if (mx >= floorVal) {                 // rare
            float xs[4] = {v.x, v.y, v.z, v.w};
            #pragma unroll
            for (int c = 0; c < 4; c++) {
                float x = xs[c];
                if (x >= floorVal) {
                    int p = atomicAdd(&s_seg[wid], 1);
                    if (p < WSEG) { cval[segBase + p] = x; cidx[segBase + p] = i4*4 + c; }
                }
            }
        }
    };
    {
        int i = tid;
        for (; i + 7*1024 < n4; i += 8*1024) {
            float4 v0 = cls4[i];          float4 v1 = cls4[i + 1024];
            float4 v2 = cls4[i + 2048];   float4 v3 = cls4[i + 3072];
            float4 v4 = cls4[i + 4096];   float4 v5 = cls4[i + 5120];
            float4 v6 = cls4[i + 6144];   float4 v7 = cls4[i + 7168];
            proc(v0, i);        proc(v1, i + 1024);
            proc(v2, i + 2048); proc(v3, i + 3072);
            proc(v4, i + 4096); proc(v5, i + 5120);
            proc(v6, i + 6144); proc(v7, i + 7168);
        }
        for (; i < n4; i += 1024) proc(cls4[i], i);
    }
    __syncthreads();

    if (tid < 32) {
        unsigned bad = __ballot_sync(FULLM, s_seg[tid] > WSEG);
        if (tid == 0) s_flags = bad;
    }
    __syncthreads();
    const bool cacheOK = (s_flags == 0);

    auto decode_store = [&](float x, int j) {
        int a = j / HW;
        int rem = j - a*HW;
        const float* bp = boxp + ((size_t)(b*9 + a) * 4) * HW + rem;
        float d0 = bp[0], d1 = bp[HW], d2 = bp[2*HW], d3 = bp[3*HW];
        float4 an = ((const float4*)anc)[j];
        float w = an.z - an.x, h = an.w - an.y;
        float cx = an.x + 0.5f*w, cy = an.y + 0.5f*h;
        d0 = fminf(fmaxf(d0, -2.0f), 2.0f);
        d1 = fminf(fmaxf(d1, -2.0f), 2.0f);
        d2 = fminf(fmaxf(d2, -2.0f), 2.0f);
        d3 = fminf(fmaxf(d3, -2.0f), 2.0f);
        float px = cx + d0*w, py = cy + d1*h;
        float pw = w * expf(d2), ph = h * expf(d3);
        float x1 = fminf(fmaxf(px - 0.5f*pw, 0.0f), 1024.0f);
        float y1 = fminf(fmaxf(py - 0.5f*ph, 0.0f), 1024.0f);
        float x2 = fminf(fmaxf(px + 0.5f*pw, 0.0f), 1024.0f);
        float y2 = fminf(fmaxf(py + 0.5f*ph, 0.0f), 1024.0f);
        float bw = x2 - x1, bh = y2 - y1;
        if (bw > 1.0f && bh > 1.0f && bw < 2000.0f && bh < 2000.0f) {
            int pos = atomicAdd(&s_cnt, 1);
            if (pos < CANDCAP) {
                unsigned lo = ((262143u - (unsigned)j) << 13) | (unsigned)pos;
                sKey[pos] = ((unsigned long long)__float_as_uint(x) << 32) | lo;
                candBox[pos] = make_float4(x1, y1, x2, y2);
            }
        }
    };

    // ---- FAST PATH: decode everything above the floor ----
    int cnt = 0;
    bool done = false;
    if (cacheOK) {
        for (int t = tid; t < NW*WSEG; t += 1024) {
            int w = t / WSEG, o = t - w*WSEG;
            if (o < s_seg[w]) decode_store(cval[t], cidx[t]);
        }
        __syncthreads();
        cnt = s_cnt;
        done = (cnt >= KPRE && cnt <= CANDCAP);
    }

    // ---- FALLBACK: exact hist + band selection, cache-based when possible ----
    if (!done) {
        hist[tid] = 0;
        __syncthreads();
        if (cacheOK) {
            for (int t = tid; t < NW*WSEG; t += 1024) {
                int w = t / WSEG, o = t - w*WSEG;
                if (o < s_seg[w]) {
                    float x = cval[t];
                    int bk = (int)(x * LSCALE); bk = bk > NB-1 ? NB-1 : bk;
                    atomicAdd(&hist[bk], 1);
                }
            }
        } else {
            for (int i = tid; i < n4; i += 1024) {
                float4 v = cls4[i];
                float xs[4] = {v.x, v.y, v.z, v.w};
                for (int c = 0; c < 4; c++) {
                    float x = xs[c];
                    if (x > 0.0f) {
                        int bk = (int)(x * LSCALE); bk = bk > NB-1 ? NB-1 : bk;
                        atomicAdd(&hist[bk], 1);
                    }
                }
            }
        }

        auto computeAbove = [&]() -> int {
            __syncthreads();
            int h = hist[tid];
            int v = h;
            #pragma unroll
            for (int off = 1; off < 32; off <<= 1) {
                int t2 = __shfl_down_sync(FULLM, v, off);
                if (lane + off < 32) v += t2;
            }
            if (lane == 0) wtot[wid] = v;
            __syncthreads();
            int tail = 0;
            for (int w = wid + 1; w < 32; w++) tail += wtot[w];
            return (v - h) + tail;
        };

        bool histFull = !cacheOK;
        int rawTarget = RAW_T0;
        int guard = 0;
        while (true) {
            if (tid == 0) s_cut = 0;
            int above = computeAbove();
            {
                int cum = above + hist[tid];
                if (cum >= rawTarget && above < rawTarget) s_cut = tid;
            }
            __syncthreads();
            int cut = s_cut;

            if (!histFull && cut < flBK) {
                for (int i = tid; i < n4; i += 1024) {
                    float4 v = cls4[i];
                    float xs[4] = {v.x, v.y, v.z, v.w};
                    for (int c = 0; c < 4; c++) {
                        float x = xs[c];
                        if (x > 0.0f && x < floorVal) {
                            int bk = (int)(x * LSCALE); bk = bk > NB-1 ? NB-1 : bk;
                            atomicAdd(&hist[bk], 1);
                        }
                    }
                }
                histFull = true;
                continue;
            }

            if (tid == 0) s_cnt = 0;
            __syncthreads();
            const float cutVal = (float)cut * (1.0f/128.0f);   // exact

            if (cacheOK && cut >= flBK) {
                for (int t = tid; t < NW*WSEG; t += 1024) {
                    int w = t / WSEG, o = t - w*WSEG;
                    if (o < s_seg[w]) {
                        float x = cval[t];
                        if (x >= cutVal) decode_store(x, cidx[t]);
                    }
                }
            } else {
                for (int i = tid; i < n4; i += 1024) {
                    float4 v = cls4[i];
                    float xs[4] = {v.x, v.y, v.z, v.w};
                    for (int c = 0; c < 4; c++) {
                        float x = xs[c];
                        if (x > 0.0f && x >= cutVal) decode_store(x, i*4 + c);
                    }
                }
            }
            __syncthreads();
            cnt = s_cnt;
            if (++guard > 8) break;
            if (cnt > CANDCAP) {
                if (rawTarget > KPRE) { rawTarget = KPRE; continue; }
                break;
            }
            if (cnt >= KPRE || cut == 0) break;
            rawTarget += (KPRE - cnt) + 32;
        }
    }

    // ---- retire upper half: sort + NMS only need 512 threads. Exited
    // threads don't count toward bar.sync -> remaining barriers are 16-warp.
    if (tid >= SORTN) return;

    int scnt = cnt < CANDCAP ? cnt : CANDCAP;
    if (tid >= scnt) sKey[tid] = 0ull;
    __syncthreads();

    // ---- bitonic sort descending, 512 elems / 512 threads ----
    {
        unsigned long long key = sKey[tid];
        __syncthreads();
        #pragma unroll
        for (int k = 2; k <= SORTN; k <<= 1) {
            bool segDesc = ((tid & k) == 0);
            #pragma unroll
            for (int j = k >> 1; j > 0; j >>= 1) {
                unsigned long long okey;
                if (j >= 32) {
                    sKey[tid] = key;
                    __syncthreads();
                    okey = sKey[tid ^ j];
                    __syncthreads();
                } else {
                    unsigned hi = __shfl_xor_sync(FULLM, (unsigned)(key >> 32), j);
                    unsigned lo = __shfl_xor_sync(FULLM, (unsigned)key, j);
                    okey = ((unsigned long long)hi << 32) | lo;
                }
                bool keepMax = (((tid & j) == 0) == segDesc);
                bool take = keepMax ? (okey > key) : (okey < key);
                if (take) key = okey;
            }
        }
        sKey[tid] = key;
        __syncthreads();
    }

    // ---- NMS: each thread holds its candidate's box in registers ----
    const int m = scnt < KPRE ? scnt : KPRE;
    float mx1 = 0, my1 = 0, mx2 = 0, my2 = 0, mar = 0;
    if (tid < m) {
        unsigned long long kk = sKey[tid];
        float4 bb = candBox[(int)(kk & 0x1FFFu)];
        mx1 = bb.x; my1 = bb.y; mx2 = bb.z; my2 = bb.w;
        mar = (bb.z - bb.x) * (bb.w - bb.y);
    }
    if (tid < 10) {
        int lo = tid * 32;
        unsigned w;
        if (m >= lo + 32) w = FULLM;
        else if (m > lo)  w = (1u << (m - lo)) - 1u;
        else              w = 0u;
        keepw[tid] = w;
    }
    if (tid == 0) s_nk = 0;
    __syncthreads();

    for (int round = 0; round <= KOUT; round++) {
        if (tid < 32) {
            unsigned v = (tid < 10) ? keepw[tid] : 0u;
            unsigned nz = __ballot_sync(FULLM, v != 0u);
            int w = __ffs(nz) - 1;
            unsigned vw = __shfl_sync(FULLM, v, (w < 0) ? 0 : w);
            if (tid == 0) s_next = nz ? (w*32 + __ffs(vw) - 1) : -1;
        }
        __syncthreads();
        int i = s_next;
        if (i < 0 || s_nk >= KOUT) break;

        unsigned long long ki = sKey[i];               // broadcast
        float4 bi = candBox[(int)(ki & 0x1FFFu)];      // broadcast
        float ba = (bi.z - bi.x) * (bi.w - bi.y);

        if (tid == 0) {
            int nk = s_nk;
            float logit = __uint_as_float((unsigned)(ki >> 32));
            float sc = 1.0f / (1.0f + expf(-logit));
            int s5 = b*200 + (lvl*10 + nk)*5;
            out[s5+0] = bi.x; out[s5+1] = bi.y;
            out[s5+2] = bi.z; out[s5+3] = bi.w;
            out[s5+4] = sc;
            if (vF) out[3200 + slot0 + nk] = 1.0f;
            else    vB[slot0 + nk] = 1;
            s_nk = nk + 1;
            atomicAnd(&keepw[i >> 5], ~(1u << (i & 31)));
        }
        if (tid > i && tid < m && ((keepw[tid >> 5] >> (tid & 31)) & 1u)) {
            float ix1 = fmaxf(bi.x, mx1), iy1 = fmaxf(bi.y, my1);
            float ix2 = fminf(bi.z, mx2), iy2 = fminf(bi.w, my2);
            float iw = fmaxf(ix2 - ix1, 0.0f), ih = fmaxf(iy2 - iy1, 0.0f);
            float inter = iw * ih;
            float iou = inter / (ba + mar - inter + 1e-9f);
            if (iou > 0.3f) atomicAnd(&keepw[tid >> 5], ~(1u << (tid & 31)));
        }
        __syncthreads();
    }
}

// ---------------------------------------------------------------------------
extern "C" void kernel_launch(void* const* d_in, const int* in_sizes, int n_in,
                              void* d_out, int out_size) {
    Ptrs P;
    if (n_in >= 2 && in_sizes[0] == 2359296 && in_sizes[1] == 9437184) {
        for (int l = 0; l < 4; l++) {
            P.cls[l] = (const float*)d_in[3*l + 0];
            P.box[l] = (const float*)d_in[3*l + 1];
            P.anc[l] = (const float*)d_in[3*l + 2];
        }
    } else if (n_in >= 1 && in_sizes[0] == 2359296) {
        for (int l = 0; l < 4; l++) {
            P.cls[l] = (const float*)d_in[l];
            P.box[l] = (const float*)d_in[4 + l];
            P.anc[l] = (const float*)d_in[8 + l];
        }
    } else {
        for (int l = 0; l < 4; l++) {
            P.anc[l] = (const float*)d_in[l];
            P.box[l] = (const float*)d_in[4 + l];
            P.cls[l] = (const float*)d_in[8 + l];
        }
    }
    detect_kernel<<<64, 1024>>>(P, (float*)d_out, out_size);
}

// round 17
// speedup vs baseline: 1.9771x; 1.1115x over previous
#include <cuda_runtime.h>
#include <math.h>

#define NB       1024
#define LSCALE   128.0f
#define KPRE     300
#define KOUT     10
#define SORTN    512
#define CANDCAP  512
#define FLATCAP  3072
#define RAW_T0   340
#define FULLM    0xFFFFFFFFu

struct Ptrs {
    const float* cls[4];
    const float* box[4];
    const float* anc[4];
};

__device__ __forceinline__ unsigned smem_u32(const void* p) {
    return (unsigned)__cvta_generic_to_shared(p);
}
__device__ __forceinline__ unsigned mapa_rank0(unsigned addr) {
    unsigned r;
    asm("mapa.shared::cluster.u32 %0, %1, %2;" : "=r"(r) : "r"(addr), "r"(0));
    return r;
}
__device__ __forceinline__ int cluster_atom_add(unsigned addr, int v) {
    int old;
    asm volatile("atom.relaxed.cluster.shared::cluster.add.u32 %0, [%1], %2;"
                 : "=r"(old) : "r"(addr), "r"(v) : "memory");
    return old;
}
__device__ __forceinline__ void cluster_st64(unsigned addr, unsigned long long v) {
    asm volatile("st.relaxed.cluster.shared::cluster.u64 [%0], %1;"
                 :: "r"(addr), "l"(v) : "memory");
}
#define CLUSTER_SYNC() do { \
    asm volatile("barrier.cluster.arrive.aligned;" ::: "memory"); \
    asm volatile("barrier.cluster.wait.aligned;" ::: "memory"); } while (0)

// Grid 112, cluster(4): CTAs 0..63 = 16 lvl0 clusters (one per batch; each
// rank streams a quarter and appends candidates into rank0's smem via DSMEM);
// CTAs 64..111 = (batch, lvl1/2/3) local CTAs. Rank0 / local CTAs then run:
// fast-path decode of the flat cache -> [300,512] guard -> 512 bitonic sort
// (key = score|~ancidx|slot, preserves lax.top_k tie order) -> NMS (320 thr).
// Exact fallback: histogram + band selection (cache-based when possible).
__global__ __launch_bounds__(1024) __cluster_dims__(4, 1, 1)
void detect_kernel(Ptrs P, float* out, int out_size) {
    const int pid = blockIdx.x;
    int b, lvl, rank;
    if (pid < 64) { b = pid >> 2; lvl = 0; rank = pid & 3; }
    else          { int q = pid - 64; b = q / 3; lvl = 1 + q % 3; rank = 0; }
    const int HW  = 16384 >> (2*lvl);
    const int N   = 9 * HW;
    const int n4  = N >> 2;
    const int quarter = (lvl == 0) ? (n4 >> 2) : n4;
    const int i0  = rank * quarter;
    const int flBK = (lvl==0) ? 354 : (lvl==1) ? 291 : (lvl==2) ? 215 : 114;
    const float floorVal = (float)flBK * (1.0f/128.0f);   // exact
    const float* cls  = P.cls[lvl] + (size_t)b * N;
    const float* boxp = P.box[lvl];
    const float* anc  = P.anc[lvl];
    const int tid = threadIdx.x, wid = tid >> 5, lane = tid & 31;

    __shared__ unsigned long long cpair[FLATCAP];   // (idx<<32)|score_bits
    __shared__ unsigned long long sKey[SORTN];
    __shared__ float4 candBox[CANDCAP];
    __shared__ int hist[NB];
    __shared__ int wtot[32];
    __shared__ int s_ccnt, s_cnt, s_cut, s_next, s_nk;
    __shared__ unsigned keepw[10];

    const bool vF = (out_size >= 3840);
    unsigned char* vB = (unsigned char*)out + 12800;
    const int slot0 = b*40 + lvl*10;

    // zero this cell's output region (rank0 only; d_out is poisoned)
    if (rank == 0) {
        int base5 = b*200 + lvl*50;
        if (tid < 50) out[base5 + tid] = 0.0f;
        if (tid >= 64 && tid < 74) {
            int k = tid - 64;
            if (vF) out[3200 + slot0 + k] = 0.0f;
            else    vB[slot0 + k] = 0;
        }
    }
    if (tid == 0) s_ccnt = 0;
    __syncthreads();
    if (lvl == 0) CLUSTER_SYNC();     // rank0's counter init visible cluster-wide

    const float4* cls4 = (const float4*)cls;
    unsigned cntA = smem_u32(&s_ccnt);
    unsigned pairA = smem_u32(cpair);
    if (lvl == 0) { cntA = mapa_rank0(cntA); pairA = mapa_rank0(pairA); }

    // ---- stream my range: filter above floor into (rank0's) flat cache ----
    auto proc = [&](float4 v, int i4) {
        float mx = fmaxf(fmaxf(v.x, v.y), fmaxf(v.z, v.w));
        if (mx >= floorVal) {                 // rare
            float xs[4] = {v.x, v.y, v.z, v.w};
            #pragma unroll
            for (int c = 0; c < 4; c++) {
                float x = xs[c];
                if (x >= floorVal) {
                    unsigned long long e =
                        ((unsigned long long)(unsigned)(i4*4 + c) << 32)
                        | (unsigned long long)__float_as_uint(x);
                    if (lvl == 0) {
                        int pos = cluster_atom_add(cntA, 1);
                        if (pos < FLATCAP) cluster_st64(pairA + (unsigned)pos*8u, e);
                    } else {
                        int pos = atomicAdd(&s_ccnt, 1);
                        if (pos < FLATCAP) cpair[pos] = e;
                    }
                }
            }
        }
    };
    {
        const int iEnd = i0 + quarter;
        int i = i0 + tid;
        for (; i + 7*1024 < iEnd; i += 8*1024) {
            float4 v0 = cls4[i];          float4 v1 = cls4[i + 1024];
            float4 v2 = cls4[i + 2048];   float4 v3 = cls4[i + 3072];
            float4 v4 = cls4[i + 4096];   float4 v5 = cls4[i + 5120];
            float4 v6 = cls4[i + 6144];   float4 v7 = cls4[i + 7168];
            proc(v0, i);        proc(v1, i + 1024);
            proc(v2, i + 2048); proc(v3, i + 3072);
            proc(v4, i + 4096); proc(v5, i + 5120);
            proc(v6, i + 6144); proc(v7, i + 7168);
        }
        for (; i < iEnd; i += 1024) proc(cls4[i], i);
    }

    if (lvl == 0) {
        CLUSTER_SYNC();               // all quarters delivered to rank0
        if (rank != 0) return;        // rank0 owns the rest
    } else {
        __syncthreads();
    }

    const int ccntRaw = s_ccnt;
    const bool cacheOK = (ccntRaw <= FLATCAP);
    const int cc = ccntRaw < FLATCAP ? ccntRaw : FLATCAP;

    auto decode_store = [&](float x, int j) {
        int a = j / HW;
        int rem = j - a*HW;
        const float* bp = boxp + ((size_t)(b*9 + a) * 4) * HW + rem;
        float d0 = bp[0], d1 = bp[HW], d2 = bp[2*HW], d3 = bp[3*HW];
        float4 an = ((const float4*)anc)[j];
        float w = an.z - an.x, h = an.w - an.y;
        float cx = an.x + 0.5f*w, cy = an.y + 0.5f*h;
        d0 = fminf(fmaxf(d0, -2.0f), 2.0f);
        d1 = fminf(fmaxf(d1, -2.0f), 2.0f);
        d2 = fminf(fmaxf(d2, -2.0f), 2.0f);
        d3 = fminf(fmaxf(d3, -2.0f), 2.0f);
        float px = cx + d0*w, py = cy + d1*h;
        float pw = w * expf(d2), ph = h * expf(d3);
        float x1 = fminf(fmaxf(px - 0.5f*pw, 0.0f), 1024.0f);
        float y1 = fminf(fmaxf(py - 0.5f*ph, 0.0f), 1024.0f);
        float x2 = fminf(fmaxf(px + 0.5f*pw, 0.0f), 1024.0f);
        float y2 = fminf(fmaxf(py + 0.5f*ph, 0.0f), 1024.0f);
        float bw = x2 - x1, bh = y2 - y1;
        if (bw > 1.0f && bh > 1.0f && bw < 2000.0f && bh < 2000.0f) {
            int pos = atomicAdd(&s_cnt, 1);
            if (pos < CANDCAP) {
                unsigned lo = ((262143u - (unsigned)j) << 13) | (unsigned)pos;
                sKey[pos] = ((unsigned long long)__float_as_uint(x) << 32) | lo;
                candBox[pos] = make_float4(x1, y1, x2, y2);
            }
        }
    };

    // ---- FAST PATH: decode everything above the floor ----
    if (tid == 0) s_cnt = 0;
    __syncthreads();
    int cnt = 0;
    bool done = false;
    if (cacheOK) {
        for (int t = tid; t < cc; t += 1024) {
            unsigned long long e = cpair[t];
            decode_store(__uint_as_float((unsigned)e), (int)(e >> 32));
        }
        __syncthreads();
        cnt = s_cnt;
        done = (cnt >= KPRE && cnt <= CANDCAP);
    }

    // ---- FALLBACK: exact hist + band selection, cache-based when possible ----
    if (!done) {
        hist[tid] = 0;
        __syncthreads();
        if (cacheOK) {
            for (int t = tid; t < cc; t += 1024) {
                float x = __uint_as_float((unsigned)cpair[t]);
                int bk = (int)(x * LSCALE); bk = bk > NB-1 ? NB-1 : bk;
                atomicAdd(&hist[bk], 1);
            }
        } else {
            for (int i = tid; i < n4; i += 1024) {
                float4 v = cls4[i];
                float xs[4] = {v.x, v.y, v.z, v.w};
                for (int c = 0; c < 4; c++) {
                    float x = xs[c];
                    if (x > 0.0f) {
                        int bk = (int)(x * LSCALE); bk = bk > NB-1 ? NB-1 : bk;
                        atomicAdd(&hist[bk], 1);
                    }
                }
            }
        }

        auto computeAbove = [&]() -> int {
            __syncthreads();
            int h = hist[tid];
            int v = h;
            #pragma unroll
            for (int off = 1; off < 32; off <<= 1) {
                int t2 = __shfl_down_sync(FULLM, v, off);
                if (lane + off < 32) v += t2;
            }
            if (lane == 0) wtot[wid] = v;
            __syncthreads();
            int tail = 0;
            for (int w = wid + 1; w < 32; w++) tail += wtot[w];
            return (v - h) + tail;
        };

        bool histFull = !cacheOK;
        int rawTarget = RAW_T0;
        int guard = 0;
        while (true) {
            if (tid == 0) s_cut = 0;
            int above = computeAbove();
            {
                int cum = above + hist[tid];
                if (cum >= rawTarget && above < rawTarget) s_cut = tid;
            }
            __syncthreads();
            int cut = s_cut;

            if (!histFull && cut < flBK) {
                for (int i = tid; i < n4; i += 1024) {
                    float4 v = cls4[i];
                    float xs[4] = {v.x, v.y, v.z, v.w};
                    for (int c = 0; c < 4; c++) {
                        float x = xs[c];
                        if (x > 0.0f && x < floorVal) {
                            int bk = (int)(x * LSCALE); bk = bk > NB-1 ? NB-1 : bk;
                            atomicAdd(&hist[bk], 1);
                        }
                    }
                }
                histFull = true;
                continue;
            }

            if (tid == 0) s_cnt = 0;
            __syncthreads();
            const float cutVal = (float)cut * (1.0f/128.0f);   // exact

            if (cacheOK && cut >= flBK) {
                for (int t = tid; t < cc; t += 1024) {
                    unsigned long long e = cpair[t];
                    float x = __uint_as_float((unsigned)e);
                    if (x >= cutVal) decode_store(x, (int)(e >> 32));
                }
            } else {
                for (int i = tid; i < n4; i += 1024) {
                    float4 v = cls4[i];
                    float xs[4] = {v.x, v.y, v.z, v.w};
                    for (int c = 0; c < 4; c++) {
                        float x = xs[c];
                        if (x > 0.0f && x >= cutVal) decode_store(x, i*4 + c);
                    }
                }
            }
            __syncthreads();
            cnt = s_cnt;
            if (++guard > 8) break;
            if (cnt > CANDCAP) {
                if (rawTarget > KPRE) { rawTarget = KPRE; continue; }
                break;
            }
            if (cnt >= KPRE || cut == 0) break;
            rawTarget += (KPRE - cnt) + 32;
        }
    }

    // ---- retire upper half: sort + NMS only need 512 threads ----
    if (tid >= SORTN) return;

    int scnt = cnt < CANDCAP ? cnt : CANDCAP;
    if (tid >= scnt) sKey[tid] = 0ull;
    __syncthreads();

    // ---- bitonic sort descending, 512 elems / 512 threads ----
    {
        unsigned long long key = sKey[tid];
        __syncthreads();
        #pragma unroll
        for (int k = 2; k <= SORTN; k <<= 1) {
            bool segDesc = ((tid & k) == 0);
            #pragma unroll
            for (int j = k >> 1; j > 0; j >>= 1) {
                unsigned long long okey;
                if (j >= 32) {
                    sKey[tid] = key;
                    __syncthreads();
                    okey = sKey[tid ^ j];
                    __syncthreads();
                } else {
                    unsigned hi = __shfl_xor_sync(FULLM, (unsigned)(key >> 32), j);
                    unsigned lo = __shfl_xor_sync(FULLM, (unsigned)key, j);
                    okey = ((unsigned long long)hi << 32) | lo;
                }
                bool keepMax = (((tid & j) == 0) == segDesc);
                bool take = keepMax ? (okey > key) : (okey < key);
                if (take) key = okey;
            }
        }
        sKey[tid] = key;
        __syncthreads();
    }

    // ---- retire to 320 threads (10 warps) for NMS ----
    if (tid >= 320) return;

    const int m = scnt < KPRE ? scnt : KPRE;
    float mx1 = 0, my1 = 0, mx2 = 0, my2 = 0, mar = 0;
    if (tid < m) {
        unsigned long long kk = sKey[tid];
        float4 bb = candBox[(int)(kk & 0x1FFFu)];
        mx1 = bb.x; my1 = bb.y; mx2 = bb.z; my2 = bb.w;
        mar = (bb.z - bb.x) * (bb.w - bb.y);
    }
    if (tid < 10) {
        int lo = tid * 32;
        unsigned w;
        if (m >= lo + 32) w = FULLM;
        else if (m > lo)  w = (1u << (m - lo)) - 1u;
        else              w = 0u;
        keepw[tid] = w;
    }
    if (tid == 0) s_nk = 0;
    __syncthreads();

    for (int round = 0; round <= KOUT; round++) {
        if (tid < 32) {
            unsigned v = (tid < 10) ? keepw[tid] : 0u;
            unsigned nz = __ballot_sync(FULLM, v != 0u);
            int w = __ffs(nz) - 1;
            unsigned vw = __shfl_sync(FULLM, v, (w < 0) ? 0 : w);
            if (tid == 0) s_next = nz ? (w*32 + __ffs(vw) - 1) : -1;
        }
        __syncthreads();
        int i = s_next;
        if (i < 0 || s_nk >= KOUT) break;

        unsigned long long ki = sKey[i];               // broadcast
        float4 bi = candBox[(int)(ki & 0x1FFFu)];      // broadcast
        float ba = (bi.z - bi.x) * (bi.w - bi.y);

        if (tid == 0) {
            int nk = s_nk;
            float logit = __uint_as_float((unsigned)(ki >> 32));
            float sc = 1.0f / (1.0f + expf(-logit));
            int s5 = b*200 + (lvl*10 + nk)*5;
            out[s5+0] = bi.x; out[s5+1] = bi.y;
            out[s5+2] = bi.z; out[s5+3] = bi.w;
            out[s5+4] = sc;
            if (vF) out[3200 + slot0 + nk] = 1.0f;
            else    vB[slot0 + nk] = 1;
            s_nk = nk + 1;
            atomicAnd(&keepw[i >> 5], ~(1u << (i & 31)));
        }
        if (tid > i && tid < m && ((keepw[tid >> 5] >> (tid & 31)) & 1u)) {
            float ix1 = fmaxf(bi.x, mx1), iy1 = fmaxf(bi.y, my1);
            float ix2 = fminf(bi.z, mx2), iy2 = fminf(bi.w, my2);
            float iw = fmaxf(ix2 - ix1, 0.0f), ih = fmaxf(iy2 - iy1, 0.0f);
            float inter = iw * ih;
            float iou = inter / (ba + mar - inter + 1e-9f);
            if (iou > 0.3f) atomicAnd(&keepw[tid >> 5], ~(1u << (tid & 31)));
        }
        __syncthreads();
    }
}

// ---------------------------------------------------------------------------
extern "C" void kernel_launch(void* const* d_in, const int* in_sizes, int n_in,
                              void* d_out, int out_size) {
    Ptrs P;
    if (n_in >= 2 && in_sizes[0] == 2359296 && in_sizes[1] == 9437184) {
        for (int l = 0; l < 4; l++) {
            P.cls[l] = (const float*)d_in[3*l + 0];
            P.box[l] = (const float*)d_in[3*l + 1];
            P.anc[l] = (const float*)d_in[3*l + 2];
        }
    } else if (n_in >= 1 && in_sizes[0] == 2359296) {
        for (int l = 0; l < 4; l++) {
            P.cls[l] = (const float*)d_in[l];
            P.box[l] = (const float*)d_in[4 + l];
            P.anc[l] = (const float*)d_in[8 + l];
        }
    } else {
        for (int l = 0; l < 4; l++) {
            P.anc[l] = (const float*)d_in[l];
            P.box[l] = (const float*)d_in[4 + l];
            P.cls[l] = (const float*)d_in[8 + l];
        }
    }
    detect_kernel<<<112, 1024>>>(P, (float*)d_out, out_size);
}